// round 2
// baseline (speedup 1.0000x reference)
#include <cuda_runtime.h>
#include <complex>
#include <cmath>
#include <cstring>

typedef unsigned long long ull;

// ---------------------------------------------------------------------------
// Problem constants
// ---------------------------------------------------------------------------
#define NCH   128
#define BATCH 16384
// DIM_IN = 9*128 = 1152 floats = 576 ull ; DIM_OUT = 16*128 = 2048 floats = 1024 ull

// ---------------------------------------------------------------------------
// Coupling table (lo, l1, l2) in the reference enumeration order
// ---------------------------------------------------------------------------
__host__ __device__ constexpr int cpl_lo(int c){ constexpr int t[18]={0,0,0,1,1,1,1,1,1,2,2,2,2,2,2,3,3,3}; return t[c]; }
__host__ __device__ constexpr int cpl_l1(int c){ constexpr int t[18]={0,1,2,0,1,1,1,2,2,0,1,1,2,2,2,1,2,2}; return t[c]; }
__host__ __device__ constexpr int cpl_l2(int c){ constexpr int t[18]={0,1,2,1,0,1,2,1,2,2,1,2,0,1,2,2,1,2}; return t[c]; }

__host__ __device__ constexpr int iabs_c(int v){ return v < 0 ? -v : v; }

// Structural nonzero superset of the real CG tensor:
// R[i,j,k] can be nonzero only if |m_k| ∈ { a+b, |a-b| } with a=|i-l1|, b=|j-l2|, m_k=|k-lo|.
// (Follows from the q-matrix sparsity pattern alone.)
__host__ __device__ constexpr bool cg_keep(int l1,int l2,int lo,int i,int j,int k){
    int a = iabs_c(i - l1), b = iabs_c(j - l2), mk = iabs_c(k - lo);
    return (mk == a + b) || (mk == iabs_c(a - b));
}

__host__ __device__ constexpr int cpl_nnz(int c){
    int l1=cpl_l1(c), l2=cpl_l2(c), lo=cpl_lo(c), n=0;
    for(int i=0;i<2*l1+1;i++)
        for(int j=0;j<2*l2+1;j++)
            for(int k=0;k<2*lo+1;k++)
                if(cg_keep(l1,l2,lo,i,j,k)) n++;
    return n;
}
__host__ __device__ constexpr int cg_off(int c){
    int o=0; for(int t=0;t<c;t++) o += cpl_nnz(t); return o;
}
constexpr int NNZ_TOTAL = cg_off(18);
static_assert(NNZ_TOTAL > 0 && NNZ_TOTAL * 8 <= 3800, "CG table must fit in kernel param space");

struct CgParams { ull v[NNZ_TOTAL]; };

// ---------------------------------------------------------------------------
// Packed f32x2 helpers (sm_103a)
// ---------------------------------------------------------------------------
__device__ __forceinline__ ull fma2(ull a, ull b, ull c){
    ull d; asm("fma.rn.f32x2 %0, %1, %2, %3;" : "=l"(d) : "l"(a), "l"(b), "l"(c)); return d;
}
__device__ __forceinline__ ull mul2(ull a, ull b){
    ull d; asm("mul.rn.f32x2 %0, %1, %2;" : "=l"(d) : "l"(a), "l"(b)); return d;
}

// ---------------------------------------------------------------------------
// One coupling: tp[k] = sum_ij p[i][j]*cg ; acc[base+k] += tp[k]*mix
// All indices compile-time after unroll; cg_s accesses are broadcast LDS.64.
// ---------------------------------------------------------------------------
template<int C>
__device__ __forceinline__ void do_cpl(const ull* p, const ull* cg_s, ull mixv, ull (&acc)[16]){
    constexpr int L1 = cpl_l1(C), L2 = cpl_l2(C), LO = cpl_lo(C);
    constexpr int BASE = (LO==0) ? 0 : (LO==1) ? 1 : (LO==2) ? 4 : 9;
    constexpr int POS0 = cg_off(C);
    ull tp[2*LO+1];
#pragma unroll
    for(int k=0;k<2*LO+1;k++) tp[k] = 0ull;
    int pos = POS0;
#pragma unroll
    for(int i=0;i<2*L1+1;i++){
#pragma unroll
        for(int j=0;j<2*L2+1;j++){
#pragma unroll
            for(int k=0;k<2*LO+1;k++){
                if(cg_keep(L1,L2,LO,i,j,k)){
                    tp[k] = fma2(p[i*(2*L2+1)+j], cg_s[pos], tp[k]);
                    pos++;
                }
            }
        }
    }
#pragma unroll
    for(int k=0;k<2*LO+1;k++) acc[BASE+k] = fma2(tp[k], mixv, acc[BASE+k]);
}

// ---------------------------------------------------------------------------
// Main kernel: 128 threads/block, 2 rows/block, 64 threads per row
// Each thread handles a channel PAIR (2n, 2n+1) with packed f32x2 math.
// ---------------------------------------------------------------------------
__global__ void __launch_bounds__(128) smix_kernel(
    const float* __restrict__ xg,
    const float* __restrict__ keepg,
    const float* __restrict__ mixg,
    float* __restrict__ outg,
    CgParams cg)
{
    __shared__ ull cg_s[NNZ_TOTAL];
    for(int t = threadIdx.x; t < NNZ_TOTAL; t += 128) cg_s[t] = cg.v[t];
    __syncthreads();

    const int tid   = threadIdx.x;
    const int local = tid & 63;                       // channel-pair index
    const long row  = (long)(blockIdx.x * 2) + (tid >> 6);

    const ull* X = (const ull*)xg   + row * 576 + local;
    const ull* K = (const ull*)keepg + local;
    const ull* M = (const ull*)mixg  + local;

    ull x0 = X[0];
    ull x1[3];
#pragma unroll
    for(int j=0;j<3;j++) x1[j] = X[64 + 64*j];
    ull x2[5];
#pragma unroll
    for(int j=0;j<5;j++) x2[j] = X[256 + 64*j];

    // accumulators: lo=0 -> acc[0]; lo=1 -> acc[1..3]; lo=2 -> acc[4..8]; lo=3 -> acc[9..15]
    ull acc[16];
    {
        ull kc0 = K[0], kc1 = K[64], kc2 = K[128];
        acc[0] = mul2(x0, kc0);
#pragma unroll
        for(int j=0;j<3;j++) acc[1+j] = mul2(x1[j], kc1);
#pragma unroll
        for(int j=0;j<5;j++) acc[4+j] = mul2(x2[j], kc2);
#pragma unroll
        for(int j=9;j<16;j++) acc[j] = 0ull;
    }

    // Pair (0,0)
    {
        ull p[1] = { mul2(x0, x0) };
        do_cpl<0>(p, cg_s, M[0*64], acc);            // (0,0,0)
    }
    // Pairs (0,1) and (1,0): p[j] = x0*x1[j]
    {
        ull p[3];
#pragma unroll
        for(int j=0;j<3;j++) p[j] = mul2(x0, x1[j]);
        do_cpl<3>(p, cg_s, M[3*64], acc);            // (1,0,1)  layout (1,3)
        do_cpl<4>(p, cg_s, M[4*64], acc);            // (1,1,0)  layout (3,1) == same array
    }
    // Pairs (0,2) and (2,0): p[j] = x0*x2[j]
    {
        ull p[5];
#pragma unroll
        for(int j=0;j<5;j++) p[j] = mul2(x0, x2[j]);
        do_cpl<9>(p, cg_s, M[9*64], acc);            // (2,0,2)
        do_cpl<12>(p, cg_s, M[12*64], acc);          // (2,2,0)
    }
    // Pair (1,1)
    {
        ull p[9];
#pragma unroll
        for(int i=0;i<3;i++)
#pragma unroll
            for(int j=0;j<3;j++) p[i*3+j] = mul2(x1[i], x1[j]);
        do_cpl<1>(p, cg_s, M[1*64], acc);            // (0,1,1)
        do_cpl<5>(p, cg_s, M[5*64], acc);            // (1,1,1)
        do_cpl<10>(p, cg_s, M[10*64], acc);          // (2,1,1)
    }
    // Pairs (1,2) and (2,1)
    {
        ull p[15];
#pragma unroll
        for(int i=0;i<3;i++)
#pragma unroll
            for(int j=0;j<5;j++) p[i*5+j] = mul2(x1[i], x2[j]);
        do_cpl<6>(p, cg_s, M[6*64], acc);            // (1,1,2)
        do_cpl<11>(p, cg_s, M[11*64], acc);          // (2,1,2)
        do_cpl<15>(p, cg_s, M[15*64], acc);          // (3,1,2)
        ull pt[15];                                   // transpose (register renames only)
#pragma unroll
        for(int i=0;i<5;i++)
#pragma unroll
            for(int j=0;j<3;j++) pt[i*3+j] = p[j*5+i];
        do_cpl<7>(pt, cg_s, M[7*64], acc);           // (1,2,1)
        do_cpl<13>(pt, cg_s, M[13*64], acc);         // (2,2,1)
        do_cpl<16>(pt, cg_s, M[16*64], acc);         // (3,2,1)
    }
    // Pair (2,2)
    {
        ull p[25];
#pragma unroll
        for(int i=0;i<5;i++)
#pragma unroll
            for(int j=0;j<5;j++) p[i*5+j] = mul2(x2[i], x2[j]);
        do_cpl<2>(p, cg_s, M[2*64], acc);            // (0,2,2)
        do_cpl<8>(p, cg_s, M[8*64], acc);            // (1,2,2)
        do_cpl<14>(p, cg_s, M[14*64], acc);          // (2,2,2)
        do_cpl<17>(p, cg_s, M[17*64], acc);          // (3,2,2)
    }

    // store: out row = [lo0: 0..63][lo1: 64..255][lo2: 256..575][lo3: 576..1023] (ull units)
    ull* O = (ull*)outg + row * 1024 + local;
    O[0] = acc[0];
#pragma unroll
    for(int k=0;k<3;k++) O[64  + 64*k] = acc[1+k];
#pragma unroll
    for(int k=0;k<5;k++) O[256 + 64*k] = acc[4+k];
#pragma unroll
    for(int k=0;k<7;k++) O[576 + 64*k] = acc[9+k];
}

// ---------------------------------------------------------------------------
// Host: compute real CG tables exactly like the reference (double precision),
// fold the 0.5 factor in, duplicate each value into both f32x2 halves, and
// emit in the exact (coupling, i, j, k) order the device template consumes.
// ---------------------------------------------------------------------------
namespace cgbuild {

using cd = std::complex<double>;

static double fct(int n){ double r = 1.0; for(int i=2;i<=n;i++) r *= (double)i; return r; }

static void qmat(int l, cd q[7][7]){
    for(int a=0;a<7;a++) for(int b=0;b<7;b++) q[a][b] = cd(0.0, 0.0);
    const double s2 = 1.0 / std::sqrt(2.0);
    for(int m=-l;m<0;m++){
        q[l+m][l-m] = cd(s2, 0.0);       // q[l+m, l+|m|] = s2
        q[l+m][l+m] = cd(0.0, -s2);      // q[l+m, l-|m|] = -i*s2
    }
    q[l][l] = cd(1.0, 0.0);
    for(int m=1;m<=l;m++){
        double sg = (m & 1) ? -1.0 : 1.0;
        q[l+m][l+m] = cd(sg * s2, 0.0);
        q[l+m][l-m] = cd(0.0, sg * s2);
    }
    cd ph = (l==0) ? cd(1,0) : (l==1) ? cd(0,-1) : (l==2) ? cd(-1,0) : cd(0,1); // (-i)^l
    for(int a=0;a<7;a++) for(int b=0;b<7;b++) q[a][b] *= ph;
}

static void build_cg(ull* v){
    int pos = 0;
    for(int c=0;c<18;c++){
        const int lo = cpl_lo(c), l1 = cpl_l1(c), l2 = cpl_l2(c);
        const int j1 = l1, j2 = l2, j3 = lo;

        // su2 CG
        double C[7][7][7] = {};
        {
            double pref_j = std::sqrt((2*j3+1) * fct(j3+j1-j2) * fct(j3-j1+j2) *
                                      fct(j1+j2-j3) / fct(j1+j2+j3+1));
            for(int m1=-j1;m1<=j1;m1++){
                for(int m2=-j2;m2<=j2;m2++){
                    int m3 = m1 + m2;
                    if(iabs_c(m3) > j3) continue;
                    double pref_m = std::sqrt(fct(j3+m3)*fct(j3-m3)*fct(j1-m1)*
                                              fct(j1+m1)*fct(j2-m2)*fct(j2+m2));
                    double s = 0.0;
                    for(int vv=0; vv<=j1+j2-j3; vv++){
                        int a = j1+j2-j3-vv, b = j1-m1-vv, cc = j2+m2-vv;
                        int d = j3-j2+m1+vv, e = j3-j1-m2+vv;
                        if(a<0 || b<0 || cc<0 || d<0 || e<0) continue;
                        double term = 1.0 / (fct(vv)*fct(a)*fct(b)*fct(cc)*fct(d)*fct(e));
                        s += (vv & 1) ? -term : term;
                    }
                    C[m1+j1][m2+j2][m3+j3] = pref_j * pref_m * s;
                }
            }
        }

        cd q1[7][7], q2[7][7], q3[7][7];
        qmat(l1, q1); qmat(l2, q2); qmat(lo, q3);

        const int d1 = 2*l1+1, d2 = 2*l2+1, d3 = 2*lo+1;
        double Rre[5][5][7], Rim[5][5][7];
        double sre = 0.0, sim = 0.0;
        for(int i=0;i<d1;i++){
            for(int j=0;j<d2;j++){
                for(int k=0;k<d3;k++){
                    cd s(0.0, 0.0);
                    for(int a=0;a<d1;a++)
                        for(int b=0;b<d2;b++)
                            for(int cc=0;cc<d3;cc++)
                                s += C[a][b][cc] * q1[a][i] * q2[b][j] * std::conj(q3[cc][k]);
                    Rre[i][j][k] = s.real();
                    Rim[i][j][k] = s.imag();
                    sre += std::fabs(s.real());
                    sim += std::fabs(s.imag());
                }
            }
        }
        const bool use_re = (sre >= sim);

        // emit in the exact device consumption order, 0.5 folded in, duplicated halves
        for(int i=0;i<d1;i++){
            for(int j=0;j<d2;j++){
                for(int k=0;k<d3;k++){
                    if(!cg_keep(l1,l2,lo,i,j,k)) continue;
                    double val = use_re ? Rre[i][j][k] : Rim[i][j][k];
                    float f = 0.5f * (float)val;
                    unsigned int u;
                    std::memcpy(&u, &f, 4);
                    v[pos++] = (ull)u | ((ull)u << 32);
                }
            }
        }
    }
}

} // namespace cgbuild

// ---------------------------------------------------------------------------
// Launch (graph-capturable: only a kernel launch; CG table passed by value)
// ---------------------------------------------------------------------------
extern "C" void kernel_launch(void* const* d_in, const int* in_sizes, int n_in,
                              void* d_out, int out_size)
{
    (void)in_sizes; (void)n_in; (void)out_size;
    const float* x    = (const float*)d_in[0];
    const float* keep = (const float*)d_in[1];
    const float* mix  = (const float*)d_in[2];

    CgParams P;
    cgbuild::build_cg(P.v);   // deterministic, recomputed every call

    // 8192 blocks * 128 threads: 2 rows/block, 64 channel-pairs/row
    smix_kernel<<<BATCH / 2, 128>>>(x, keep, mix, (float*)d_out, P);
}

// round 3
// speedup vs baseline: 2.4463x; 2.4463x over previous
#include <cuda_runtime.h>

typedef unsigned long long ull;

#define NCH   128
#define BATCH 16384
// DIM_IN = 1152 floats/row ; DIM_OUT = 2048 floats/row

// ---------------------------------------------------------------------------
// Coupling table (lo, l1, l2) in the reference enumeration order
// ---------------------------------------------------------------------------
__host__ __device__ constexpr int cpl_lo(int c){ constexpr int t[18]={0,0,0,1,1,1,1,1,1,2,2,2,2,2,2,3,3,3}; return t[c]; }
__host__ __device__ constexpr int cpl_l1(int c){ constexpr int t[18]={0,1,2,0,1,1,1,2,2,0,1,1,2,2,2,1,2,2}; return t[c]; }
__host__ __device__ constexpr int cpl_l2(int c){ constexpr int t[18]={0,1,2,1,0,1,2,1,2,2,1,2,0,1,2,2,1,2}; return t[c]; }

__host__ __device__ constexpr int iabs_c(int v){ return v < 0 ? -v : v; }

// Structural nonzero superset of the real CG tensor (from q-matrix sparsity).
__host__ __device__ constexpr bool cg_keep(int l1,int l2,int lo,int i,int j,int k){
    int a = iabs_c(i - l1), b = iabs_c(j - l2), mk = iabs_c(k - lo);
    return (mk == a + b) || (mk == iabs_c(a - b));
}

// ---------------------------------------------------------------------------
// Compile-time CG table: constexpr port of the reference (double precision),
// 0.5 folded in. Values become FFMA immediates in SASS (rt_SMSP = 1).
// ---------------------------------------------------------------------------
__host__ __device__ constexpr double cfabs_c(double x){ return x < 0 ? -x : x; }
__host__ __device__ constexpr double csqrt_c(double x){
    double g = x > 1.0 ? x : 1.0;
    for(int i=0;i<64;i++) g = 0.5*(g + x/g);
    return g;
}
__host__ __device__ constexpr double fct_c(int n){ double r = 1.0; for(int i=2;i<=n;i++) r *= (double)i; return r; }

struct Cplx { double re, im; };
__host__ __device__ constexpr Cplx cmul(Cplx a, Cplx b){ return Cplx{a.re*b.re - a.im*b.im, a.re*b.im + a.im*b.re}; }
__host__ __device__ constexpr Cplx cadd(Cplx a, Cplx b){ return Cplx{a.re + b.re, a.im + b.im}; }
__host__ __device__ constexpr Cplx cconj(Cplx a){ return Cplx{a.re, -a.im}; }
__host__ __device__ constexpr Cplx cscal(double s, Cplx a){ return Cplx{s*a.re, s*a.im}; }

struct CgTable { float v[18][5][5][7]; };

__host__ __device__ constexpr CgTable build_cg_table(){
    CgTable T{};
    for(int c=0;c<18;c++){
        const int lo = cpl_lo(c), l1 = cpl_l1(c), l2 = cpl_l2(c);

        // SU(2) Clebsch-Gordan
        double C[7][7][7] = {};
        {
            double pref_j = csqrt_c((2*lo+1) * fct_c(lo+l1-l2) * fct_c(lo-l1+l2) *
                                    fct_c(l1+l2-lo) / fct_c(l1+l2+lo+1));
            for(int m1=-l1;m1<=l1;m1++){
                for(int m2=-l2;m2<=l2;m2++){
                    int m3 = m1 + m2;
                    if(m3 < -lo || m3 > lo) continue;
                    double pref_m = csqrt_c(fct_c(lo+m3)*fct_c(lo-m3)*fct_c(l1-m1)*
                                            fct_c(l1+m1)*fct_c(l2-m2)*fct_c(l2+m2));
                    double s = 0.0;
                    for(int vv=0; vv<=l1+l2-lo; vv++){
                        int a = l1+l2-lo-vv, b = l1-m1-vv, cc = l2+m2-vv;
                        int d = lo-l2+m1+vv, e = lo-l1-m2+vv;
                        if(a<0 || b<0 || cc<0 || d<0 || e<0) continue;
                        double term = 1.0 / (fct_c(vv)*fct_c(a)*fct_c(b)*fct_c(cc)*fct_c(d)*fct_c(e));
                        s += (vv & 1) ? -term : term;
                    }
                    C[m1+l1][m2+l2][m3+lo] = pref_j * pref_m * s;
                }
            }
        }

        // q matrices for l1, l2, lo
        Cplx q[3][7][7] = {};
        const int ls[3] = {l1, l2, lo};
        for(int t=0;t<3;t++){
            const int l = ls[t];
            const double s2 = 1.0 / csqrt_c(2.0);
            for(int m=-l;m<0;m++){
                q[t][l+m][l-m] = Cplx{s2, 0.0};       // column l+|m|
                q[t][l+m][l+m] = Cplx{0.0, -s2};      // column l-|m|
            }
            q[t][l][l] = Cplx{1.0, 0.0};
            for(int m=1;m<=l;m++){
                double sg = (m & 1) ? -1.0 : 1.0;
                q[t][l+m][l+m] = Cplx{sg*s2, 0.0};
                q[t][l+m][l-m] = Cplx{0.0, sg*s2};
            }
            // (-i)^l
            Cplx ph = (l==0) ? Cplx{1,0} : (l==1) ? Cplx{0,-1} : (l==2) ? Cplx{-1,0} : Cplx{0,1};
            for(int a=0;a<7;a++) for(int b=0;b<7;b++) q[t][a][b] = cmul(q[t][a][b], ph);
        }

        const int d1 = 2*l1+1, d2 = 2*l2+1, d3 = 2*lo+1;
        double Rre[5][5][7] = {}, Rim[5][5][7] = {};
        double sre = 0.0, sim = 0.0;
        for(int i=0;i<d1;i++){
            for(int j=0;j<d2;j++){
                for(int k=0;k<d3;k++){
                    Cplx s{0.0, 0.0};
                    for(int a=0;a<d1;a++)
                        for(int b=0;b<d2;b++)
                            for(int cc=0;cc<d3;cc++){
                                if(C[a][b][cc] == 0.0) continue;
                                s = cadd(s, cscal(C[a][b][cc],
                                        cmul(cmul(q[0][a][i], q[1][b][j]), cconj(q[2][cc][k]))));
                            }
                    Rre[i][j][k] = s.re; Rim[i][j][k] = s.im;
                    sre += cfabs_c(s.re); sim += cfabs_c(s.im);
                }
            }
        }
        const bool use_re = (sre >= sim);
        for(int i=0;i<d1;i++)
            for(int j=0;j<d2;j++)
                for(int k=0;k<d3;k++){
                    double val = use_re ? Rre[i][j][k] : Rim[i][j][k];
                    T.v[c][i][j][k] = 0.5f * (float)val;
                }
    }
    return T;
}

constexpr CgTable CG = build_cg_table();

// ---------------------------------------------------------------------------
// Compile-time unrolled contraction: each nonzero CG becomes FFMA R,R,imm,R.
// ---------------------------------------------------------------------------
template<int C, int N, int TOTAL>
struct CgLoop {
    __device__ __forceinline__ static void run(const float* p, float* tp){
        constexpr int L1 = cpl_l1(C), L2 = cpl_l2(C), LO = cpl_lo(C);
        constexpr int D2 = 2*L2+1, D3 = 2*LO+1;
        constexpr int I = N / (D2*D3), J = (N / D3) % D2, K = N % D3;
        if constexpr (cg_keep(L1, L2, LO, I, J, K)){
            constexpr float cgv = CG.v[C][I][J][K];
            if constexpr (cgv != 0.0f){
                tp[K] = fmaf(p[I*D2 + J], cgv, tp[K]);
            }
        }
        CgLoop<C, N+1, TOTAL>::run(p, tp);
    }
};
template<int C, int TOTAL>
struct CgLoop<C, TOTAL, TOTAL> {
    __device__ __forceinline__ static void run(const float*, float*){}
};

template<int C>
__device__ __forceinline__ void do_cpl(const float* p, float mixv, float (&acc)[16]){
    constexpr int L1 = cpl_l1(C), L2 = cpl_l2(C), LO = cpl_lo(C);
    constexpr int BASE = (LO==0) ? 0 : (LO==1) ? 1 : (LO==2) ? 4 : 9;
    float tp[2*LO+1];
#pragma unroll
    for(int k=0;k<2*LO+1;k++) tp[k] = 0.0f;
    CgLoop<C, 0, (2*L1+1)*(2*L2+1)*(2*LO+1)>::run(p, tp);
#pragma unroll
    for(int k=0;k<2*LO+1;k++) acc[BASE+k] = fmaf(tp[k], mixv, acc[BASE+k]);
}

// ---------------------------------------------------------------------------
// Kernel: 256 threads/block = 2 rows; 1 channel per thread; no shared memory.
// ---------------------------------------------------------------------------
__global__ void __launch_bounds__(256) smix_kernel(
    const float* __restrict__ xg,
    const float* __restrict__ keepg,
    const float* __restrict__ mixg,
    float* __restrict__ outg)
{
    const int tid = threadIdx.x;
    const int ch  = tid & 127;                         // channel
    const long row = (long)(blockIdx.x * 2) + (tid >> 7);

    const float* X = xg + row * 1152 + ch;

    float x0 = X[0];
    float x1[3];
#pragma unroll
    for(int j=0;j<3;j++) x1[j] = X[128 + 128*j];
    float x2[5];
#pragma unroll
    for(int j=0;j<5;j++) x2[j] = X[512 + 128*j];

    const float* M = mixg + ch;

    // accumulators: lo=0 -> acc[0]; lo=1 -> acc[1..3]; lo=2 -> acc[4..8]; lo=3 -> acc[9..15]
    float acc[16];
    {
        float kc0 = keepg[ch], kc1 = keepg[128 + ch], kc2 = keepg[256 + ch];
        acc[0] = x0 * kc0;
#pragma unroll
        for(int j=0;j<3;j++) acc[1+j] = x1[j] * kc1;
#pragma unroll
        for(int j=0;j<5;j++) acc[4+j] = x2[j] * kc2;
#pragma unroll
        for(int j=9;j<16;j++) acc[j] = 0.0f;
    }

    // Pair (0,0)
    {
        float p[1] = { x0 * x0 };
        do_cpl<0>(p, M[0*128], acc);                  // (0,0,0)
    }
    // Pairs (0,1) and (1,0)
    {
        float p[3];
#pragma unroll
        for(int j=0;j<3;j++) p[j] = x0 * x1[j];
        do_cpl<3>(p, M[3*128], acc);                  // (1,0,1) layout (1,3)
        do_cpl<4>(p, M[4*128], acc);                  // (1,1,0) layout (3,1) == same array
    }
    // Pairs (0,2) and (2,0)
    {
        float p[5];
#pragma unroll
        for(int j=0;j<5;j++) p[j] = x0 * x2[j];
        do_cpl<9>(p, M[9*128], acc);                  // (2,0,2)
        do_cpl<12>(p, M[12*128], acc);                // (2,2,0)
    }
    // Pair (1,1)
    {
        float p[9];
#pragma unroll
        for(int i=0;i<3;i++)
#pragma unroll
            for(int j=0;j<3;j++) p[i*3+j] = x1[i] * x1[j];
        do_cpl<1>(p, M[1*128], acc);                  // (0,1,1)
        do_cpl<5>(p, M[5*128], acc);                  // (1,1,1)
        do_cpl<10>(p, M[10*128], acc);                // (2,1,1)
    }
    // Pairs (1,2) and (2,1)
    {
        float p[15];
#pragma unroll
        for(int i=0;i<3;i++)
#pragma unroll
            for(int j=0;j<5;j++) p[i*5+j] = x1[i] * x2[j];
        do_cpl<6>(p,  M[6*128],  acc);                // (1,1,2)
        do_cpl<11>(p, M[11*128], acc);                // (2,1,2)
        do_cpl<15>(p, M[15*128], acc);                // (3,1,2)
        float pt[15];                                  // register renames only
#pragma unroll
        for(int i=0;i<5;i++)
#pragma unroll
            for(int j=0;j<3;j++) pt[i*3+j] = p[j*5+i];
        do_cpl<7>(pt,  M[7*128],  acc);               // (1,2,1)
        do_cpl<13>(pt, M[13*128], acc);               // (2,2,1)
        do_cpl<16>(pt, M[16*128], acc);               // (3,2,1)
    }
    // Pair (2,2)
    {
        float p[25];
#pragma unroll
        for(int i=0;i<5;i++)
#pragma unroll
            for(int j=0;j<5;j++) p[i*5+j] = x2[i] * x2[j];
        do_cpl<2>(p,  M[2*128],  acc);                // (0,2,2)
        do_cpl<8>(p,  M[8*128],  acc);                // (1,2,2)
        do_cpl<14>(p, M[14*128], acc);                // (2,2,2)
        do_cpl<17>(p, M[17*128], acc);                // (3,2,2)
    }

    // out row layout: lo0 @0, lo1 @128 (3x128), lo2 @512 (5x128), lo3 @1152 (7x128)
    float* O = outg + row * 2048 + ch;
    O[0] = acc[0];
#pragma unroll
    for(int k=0;k<3;k++) O[128  + 128*k] = acc[1+k];
#pragma unroll
    for(int k=0;k<5;k++) O[512  + 128*k] = acc[4+k];
#pragma unroll
    for(int k=0;k<7;k++) O[1152 + 128*k] = acc[9+k];
}

// ---------------------------------------------------------------------------
// Launch: single kernel, no params beyond pointers -> trivially capturable.
// ---------------------------------------------------------------------------
extern "C" void kernel_launch(void* const* d_in, const int* in_sizes, int n_in,
                              void* d_out, int out_size)
{
    (void)in_sizes; (void)n_in; (void)out_size;
    const float* x    = (const float*)d_in[0];
    const float* keep = (const float*)d_in[1];
    const float* mix  = (const float*)d_in[2];

    smix_kernel<<<BATCH / 2, 256>>>(x, keep, mix, (float*)d_out);
}

// round 4
// speedup vs baseline: 2.6242x; 1.0727x over previous
#include <cuda_runtime.h>

#define NCH   128
#define BATCH 16384
// DIM_IN = 1152 floats/row ; DIM_OUT = 2048 floats/row

// ---------------------------------------------------------------------------
// Coupling table (lo, l1, l2) in the reference enumeration order
// ---------------------------------------------------------------------------
__host__ __device__ constexpr int cpl_lo(int c){ constexpr int t[18]={0,0,0,1,1,1,1,1,1,2,2,2,2,2,2,3,3,3}; return t[c]; }
__host__ __device__ constexpr int cpl_l1(int c){ constexpr int t[18]={0,1,2,0,1,1,1,2,2,0,1,1,2,2,2,1,2,2}; return t[c]; }
__host__ __device__ constexpr int cpl_l2(int c){ constexpr int t[18]={0,1,2,1,0,1,2,1,2,2,1,2,0,1,2,2,1,2}; return t[c]; }

// ---------------------------------------------------------------------------
// Compile-time CG table (constexpr port of reference, double precision, 0.5
// folded in). Every nonzero becomes an FFMA/FMUL immediate in SASS.
// ---------------------------------------------------------------------------
__host__ __device__ constexpr double cfabs_c(double x){ return x < 0 ? -x : x; }
__host__ __device__ constexpr double csqrt_c(double x){
    double g = x > 1.0 ? x : 1.0;
    for(int i=0;i<64;i++) g = 0.5*(g + x/g);
    return g;
}
__host__ __device__ constexpr double fct_c(int n){ double r = 1.0; for(int i=2;i<=n;i++) r *= (double)i; return r; }

struct Cplx { double re, im; };
__host__ __device__ constexpr Cplx cmul(Cplx a, Cplx b){ return Cplx{a.re*b.re - a.im*b.im, a.re*b.im + a.im*b.re}; }
__host__ __device__ constexpr Cplx cadd(Cplx a, Cplx b){ return Cplx{a.re + b.re, a.im + b.im}; }
__host__ __device__ constexpr Cplx cconj(Cplx a){ return Cplx{a.re, -a.im}; }
__host__ __device__ constexpr Cplx cscal(double s, Cplx a){ return Cplx{s*a.re, s*a.im}; }

struct CgTable { float v[18][5][5][7]; };

__host__ __device__ constexpr CgTable build_cg_table(){
    CgTable T{};
    for(int c=0;c<18;c++){
        const int lo = cpl_lo(c), l1 = cpl_l1(c), l2 = cpl_l2(c);

        double C[7][7][7] = {};
        {
            double pref_j = csqrt_c((2*lo+1) * fct_c(lo+l1-l2) * fct_c(lo-l1+l2) *
                                    fct_c(l1+l2-lo) / fct_c(l1+l2+lo+1));
            for(int m1=-l1;m1<=l1;m1++){
                for(int m2=-l2;m2<=l2;m2++){
                    int m3 = m1 + m2;
                    if(m3 < -lo || m3 > lo) continue;
                    double pref_m = csqrt_c(fct_c(lo+m3)*fct_c(lo-m3)*fct_c(l1-m1)*
                                            fct_c(l1+m1)*fct_c(l2-m2)*fct_c(l2+m2));
                    double s = 0.0;
                    for(int vv=0; vv<=l1+l2-lo; vv++){
                        int a = l1+l2-lo-vv, b = l1-m1-vv, cc = l2+m2-vv;
                        int d = lo-l2+m1+vv, e = lo-l1-m2+vv;
                        if(a<0 || b<0 || cc<0 || d<0 || e<0) continue;
                        double term = 1.0 / (fct_c(vv)*fct_c(a)*fct_c(b)*fct_c(cc)*fct_c(d)*fct_c(e));
                        s += (vv & 1) ? -term : term;
                    }
                    C[m1+l1][m2+l2][m3+lo] = pref_j * pref_m * s;
                }
            }
        }

        Cplx q[3][7][7] = {};
        const int ls[3] = {l1, l2, lo};
        for(int t=0;t<3;t++){
            const int l = ls[t];
            const double s2 = 1.0 / csqrt_c(2.0);
            for(int m=-l;m<0;m++){
                q[t][l+m][l-m] = Cplx{s2, 0.0};
                q[t][l+m][l+m] = Cplx{0.0, -s2};
            }
            q[t][l][l] = Cplx{1.0, 0.0};
            for(int m=1;m<=l;m++){
                double sg = (m & 1) ? -1.0 : 1.0;
                q[t][l+m][l+m] = Cplx{sg*s2, 0.0};
                q[t][l+m][l-m] = Cplx{0.0, sg*s2};
            }
            Cplx ph = (l==0) ? Cplx{1,0} : (l==1) ? Cplx{0,-1} : (l==2) ? Cplx{-1,0} : Cplx{0,1};
            for(int a=0;a<7;a++) for(int b=0;b<7;b++) q[t][a][b] = cmul(q[t][a][b], ph);
        }

        const int d1 = 2*l1+1, d2 = 2*l2+1, d3 = 2*lo+1;
        double Rre[5][5][7] = {}, Rim[5][5][7] = {};
        double sre = 0.0, sim = 0.0;
        for(int i=0;i<d1;i++)
            for(int j=0;j<d2;j++)
                for(int k=0;k<d3;k++){
                    Cplx s{0.0, 0.0};
                    for(int a=0;a<d1;a++)
                        for(int b=0;b<d2;b++)
                            for(int cc=0;cc<d3;cc++){
                                if(C[a][b][cc] == 0.0) continue;
                                s = cadd(s, cscal(C[a][b][cc],
                                        cmul(cmul(q[0][a][i], q[1][b][j]), cconj(q[2][cc][k]))));
                            }
                    Rre[i][j][k] = s.re; Rim[i][j][k] = s.im;
                    sre += cfabs_c(s.re); sim += cfabs_c(s.im);
                }
        const bool use_re = (sre >= sim);
        for(int i=0;i<d1;i++)
            for(int j=0;j<d2;j++)
                for(int k=0;k<d3;k++){
                    double val = use_re ? Rre[i][j][k] : Rim[i][j][k];
                    T.v[c][i][j][k] = 0.5f * (float)val;
                }
    }
    return T;
}

constexpr CgTable CG = build_cg_table();

// ---------------------------------------------------------------------------
// Compile-time helpers: symmetric folding, first-nonzero detection
// ---------------------------------------------------------------------------
// upper-triangle enumeration (i<=j), t = running index
__host__ __device__ constexpr int tri_i(int d, int t){
    int i = 0, rem = t;
    while(rem >= d - i){ rem -= d - i; i++; }
    return i;
}
__host__ __device__ constexpr int tri_j(int d, int t){
    int i = 0, rem = t;
    while(rem >= d - i){ rem -= d - i; i++; }
    return i + rem;
}

// folded coefficient for same-input (l1==l2) couplings, i<=j
__host__ __device__ constexpr float cg_symv(int c, int i, int j, int k){
    return (i == j) ? CG.v[c][i][j][k] : (CG.v[c][i][j][k] + CG.v[c][j][i][k]);
}

// first nonzero linear index N = (i*d2+j)*d3 + K for slot K (asymmetric)
__host__ __device__ constexpr int first_nz_asym(int c, int K){
    const int d1 = 2*cpl_l1(c)+1, d2 = 2*cpl_l2(c)+1, d3 = 2*cpl_lo(c)+1;
    for(int i=0;i<d1;i++)
        for(int j=0;j<d2;j++)
            if(CG.v[c][i][j][K] != 0.0f) return (i*d2+j)*d3 + K;
    return -1;
}
// first nonzero triangle index t for slot K (symmetric/folded)
__host__ __device__ constexpr int first_nz_sym(int c, int K){
    const int d = 2*cpl_l1(c)+1;
    int t = 0;
    for(int i=0;i<d;i++)
        for(int j=i;j<d;j++,t++)
            if(cg_symv(c,i,j,K) != 0.0f) return t;
    return -1;
}
__host__ __device__ constexpr bool cpl_any(int c, bool sym){
    const int d3 = 2*cpl_lo(c)+1;
    for(int k=0;k<d3;k++)
        if((sym ? first_nz_sym(c,k) : first_nz_asym(c,k)) >= 0) return true;
    return false;
}

// ---------------------------------------------------------------------------
// Unrolled contraction loops (template recursion, all indices compile-time)
// ---------------------------------------------------------------------------
template<int C, bool TRANS, int N, int TOTAL>
struct ALoop {
    __device__ __forceinline__ static void run(const float* __restrict__ p, float* tp){
        constexpr int D1 = 2*cpl_l1(C)+1, D2 = 2*cpl_l2(C)+1, D3 = 2*cpl_lo(C)+1;
        constexpr int I = N/(D2*D3), J = (N/D3)%D2, K = N%D3;
        constexpr float cgv = CG.v[C][I][J][K];
        if constexpr (cgv != 0.0f){
            constexpr int pidx = TRANS ? (J*D1 + I) : (I*D2 + J);
            if constexpr (N == first_nz_asym(C, K))
                tp[K] = p[pidx] * cgv;                // first term: FMUL-imm
            else
                tp[K] = fmaf(p[pidx], cgv, tp[K]);    // FFMA-imm (rt=1)
        }
        ALoop<C, TRANS, N+1, TOTAL>::run(p, tp);
    }
};
template<int C, bool TRANS, int TOTAL>
struct ALoop<C, TRANS, TOTAL, TOTAL> {
    __device__ __forceinline__ static void run(const float*, float*){}
};

template<int C, int N, int TOTAL>
struct SLoop {
    __device__ __forceinline__ static void run(const float* __restrict__ pu, float* tp){
        constexpr int D = 2*cpl_l1(C)+1, D3 = 2*cpl_lo(C)+1;
        constexpr int t = N/D3, K = N%D3;
        constexpr int I = tri_i(D, t), J = tri_j(D, t);
        constexpr float cgv = cg_symv(C, I, J, K);
        if constexpr (cgv != 0.0f){
            if constexpr (t == first_nz_sym(C, K))
                tp[K] = pu[t] * cgv;
            else
                tp[K] = fmaf(pu[t], cgv, tp[K]);
        }
        SLoop<C, N+1, TOTAL>::run(pu, tp);
    }
};
template<int C, int TOTAL>
struct SLoop<C, TOTAL, TOTAL> {
    __device__ __forceinline__ static void run(const float*, float*){}
};

template<int C, bool SYM, bool INIT, int K, int D3>
struct MixLoop {
    __device__ __forceinline__ static void run(const float* tp, float mixv, float (&acc)[16]){
        constexpr int LO = cpl_lo(C);
        constexpr int BASE = (LO==0) ? 0 : (LO==1) ? 1 : (LO==2) ? 4 : 9;
        constexpr bool anyk = SYM ? (first_nz_sym(C,K) >= 0) : (first_nz_asym(C,K) >= 0);
        if constexpr (anyk){
            if constexpr (INIT) acc[BASE+K] = tp[K] * mixv;
            else                acc[BASE+K] = fmaf(tp[K], mixv, acc[BASE+K]);
        } else if constexpr (INIT){
            acc[BASE+K] = 0.0f;
        }
        MixLoop<C, SYM, INIT, K+1, D3>::run(tp, mixv, acc);
    }
};
template<int C, bool SYM, bool INIT, int D3>
struct MixLoop<C, SYM, INIT, D3, D3> {
    __device__ __forceinline__ static void run(const float*, float, float (&)[16]){}
};

template<int C, bool SYM, bool TRANS, bool INIT>
__device__ __forceinline__ void do_cpl(const float* __restrict__ p,
                                       const float* __restrict__ Mch,
                                       float (&acc)[16])
{
    constexpr int D3 = 2*cpl_lo(C)+1;
    if constexpr (cpl_any(C, SYM)){
        float tp[D3];
        if constexpr (SYM){
            constexpr int D = 2*cpl_l1(C)+1, TRI = D*(D+1)/2;
            SLoop<C, 0, TRI*D3>::run(p, tp);
        } else {
            constexpr int D1 = 2*cpl_l1(C)+1, D2 = 2*cpl_l2(C)+1;
            ALoop<C, TRANS, 0, D1*D2*D3>::run(p, tp);
        }
        const float mixv = Mch[C*128];
        MixLoop<C, SYM, INIT, 0, D3>::run(tp, mixv, acc);
    } else if constexpr (INIT){
        float dummy[1];
        MixLoop<C, SYM, INIT, 0, D3>::run(dummy, 0.0f, acc);  // zero-fills acc slots
    }
}

// ---------------------------------------------------------------------------
// Kernel: 128 threads/block = 1 row; 1 channel per thread; no shared memory.
// ---------------------------------------------------------------------------
__global__ void __launch_bounds__(128, 11) smix_kernel(
    const float* __restrict__ xg,
    const float* __restrict__ keepg,
    const float* __restrict__ mixg,
    float* __restrict__ outg)
{
    const int ch  = threadIdx.x;
    const long row = blockIdx.x;

    const float* X = xg + row * 1152 + ch;
    const float* M = mixg + ch;

    float x0 = X[0];
    float x1[3];
#pragma unroll
    for(int j=0;j<3;j++) x1[j] = X[128 + 128*j];
    float x2[5];
#pragma unroll
    for(int j=0;j<5;j++) x2[j] = X[512 + 128*j];

    // accumulators: lo=0 -> acc[0]; lo=1 -> acc[1..3]; lo=2 -> acc[4..8]; lo=3 -> acc[9..15]
    float acc[16];
    {
        float kc0 = keepg[ch], kc1 = keepg[128 + ch], kc2 = keepg[256 + ch];
        acc[0] = x0 * kc0;
#pragma unroll
        for(int j=0;j<3;j++) acc[1+j] = x1[j] * kc1;
#pragma unroll
        for(int j=0;j<5;j++) acc[4+j] = x2[j] * kc2;
        // acc[9..15] initialized by the first lo=3 coupling (INIT=true)
    }

    // ---- coupling evaluation, grouped by shared pair-products ----
    // (0,0): scalar product
    {
        float p[1] = { x0 * x0 };
        do_cpl<0, false, false, false>(p, M, acc);            // (0,0,0)
    }
    // x0 * x1
    {
        float p[3];
#pragma unroll
        for(int j=0;j<3;j++) p[j] = x0 * x1[j];
        do_cpl<3, false, false, false>(p, M, acc);            // (1,0,1)
        do_cpl<4, false, false, false>(p, M, acc);            // (1,1,0)
    }
    // x0 * x2
    {
        float p[5];
#pragma unroll
        for(int j=0;j<5;j++) p[j] = x0 * x2[j];
        do_cpl<9,  false, false, false>(p, M, acc);           // (2,0,2)
        do_cpl<12, false, false, false>(p, M, acc);           // (2,2,0)
    }
    // x1 ⊗ x1 (same input -> symmetric fold; (1,1,1) cancels to zero)
    {
        float pu[6];
        {
            int t = 0;
#pragma unroll
            for(int i=0;i<3;i++)
#pragma unroll
                for(int j=i;j<3;j++) pu[t++] = x1[i] * x1[j];
        }
        do_cpl<1,  true, false, false>(pu, M, acc);           // (0,1,1)
        do_cpl<5,  true, false, false>(pu, M, acc);           // (1,1,1) -> vanishes
        do_cpl<10, true, false, false>(pu, M, acc);           // (2,1,1)
    }
    // x1 ⊗ x2 (shared by 6 couplings; 3 use the transposed view)
    {
        float p[15];
#pragma unroll
        for(int i=0;i<3;i++)
#pragma unroll
            for(int j=0;j<5;j++) p[i*5+j] = x1[i] * x2[j];
        do_cpl<6,  false, false, false>(p, M, acc);           // (1,1,2)
        do_cpl<11, false, false, false>(p, M, acc);           // (2,1,2)
        do_cpl<15, false, false, true >(p, M, acc);           // (3,1,2)  INIT lo=3 accs
        do_cpl<7,  false, true,  false>(p, M, acc);           // (1,2,1)  transposed
        do_cpl<13, false, true,  false>(p, M, acc);           // (2,2,1)  transposed
        do_cpl<16, false, true,  false>(p, M, acc);           // (3,2,1)  transposed
    }
    // x2 ⊗ x2 (symmetric fold; (1,2,2) and (3,2,2) cancel to zero)
    {
        float pu[15];
        {
            int t = 0;
#pragma unroll
            for(int i=0;i<5;i++)
#pragma unroll
                for(int j=i;j<5;j++) pu[t++] = x2[i] * x2[j];
        }
        do_cpl<2,  true, false, false>(pu, M, acc);           // (0,2,2)
        do_cpl<8,  true, false, false>(pu, M, acc);           // (1,2,2) -> vanishes
        do_cpl<14, true, false, false>(pu, M, acc);           // (2,2,2)
        do_cpl<17, true, false, false>(pu, M, acc);           // (3,2,2) -> vanishes
    }

    // out row layout: lo0 @0, lo1 @128 (3x128), lo2 @512 (5x128), lo3 @1152 (7x128)
    float* O = outg + row * 2048 + ch;
    O[0] = acc[0];
#pragma unroll
    for(int k=0;k<3;k++) O[128  + 128*k] = acc[1+k];
#pragma unroll
    for(int k=0;k<5;k++) O[512  + 128*k] = acc[4+k];
#pragma unroll
    for(int k=0;k<7;k++) O[1152 + 128*k] = acc[9+k];
}

// ---------------------------------------------------------------------------
// Launch: single kernel, pointers only -> trivially graph-capturable.
// ---------------------------------------------------------------------------
extern "C" void kernel_launch(void* const* d_in, const int* in_sizes, int n_in,
                              void* d_out, int out_size)
{
    (void)in_sizes; (void)n_in; (void)out_size;
    const float* x    = (const float*)d_in[0];
    const float* keep = (const float*)d_in[1];
    const float* mix  = (const float*)d_in[2];

    smix_kernel<<<BATCH, 128>>>(x, keep, mix, (float*)d_out);
}